// round 1
// baseline (speedup 1.0000x reference)
#include <cuda_runtime.h>
#include <math.h>

#define BB   8
#define NN   512
#define DD   128
#define HH   64
#define FNN  3
#define BN   4096          // BB*NN
#define MAXDEG 192

// ---------------- device scratch (no allocations allowed) ----------------
__device__ float g_wm1;
__device__ float g_kap[BN];
__device__ float g_f[FNN][BN];
__device__ int   g_rank[BN];
__device__ int   g_cnt[BN];
__device__ int   g_adj[BN][MAXDEG];
__device__ float g_af[FNN][BN],  g_af2[FNN][BN];
__device__ float g_gam[FNN][BN], g_df[FNN][BN], g_fdf[FNN][BN];
__device__ float g_ag[FNN][BN],  g_adf[FNN][BN], g_afdf[FNN][BN];
__device__ float g_h[3][BN * HH];
__device__ float g_agg[BN * DD];

// ---------------- wm1 = weight_mlp(1.0) scalar ----------------
__global__ void k_wm1(const float* __restrict__ W1, const float* __restrict__ b1,
                      const float* __restrict__ W2, const float* __restrict__ b2,
                      const float* __restrict__ W3, const float* __restrict__ b3) {
    __shared__ float h1[64], h2[32];
    int t = threadIdx.x;
    h1[t] = fmaxf(W1[t] + b1[t], 0.f);
    __syncthreads();
    if (t < 32) {
        float s = b2[t];
        for (int k = 0; k < 64; k++) s = fmaf(h1[k], W2[k * 32 + t], s);
        h2[t] = fmaxf(s, 0.f);
    }
    __syncthreads();
    if (t == 0) {
        float s = b3[0];
        for (int k = 0; k < 32; k++) s = fmaf(h2[k], W3[k], s);
        g_wm1 = 1.f / (1.f + expf(-s));
    }
}

// ---------------- per-node MLPs: kappa + f0..f2 ----------------
__global__ void k_node(const float* __restrict__ X,
                       const float* __restrict__ cW1, const float* __restrict__ cb1,
                       const float* __restrict__ cW2, const float* __restrict__ cb2,
                       const float* __restrict__ fW1, const float* __restrict__ fb1,
                       const float* __restrict__ fW2, const float* __restrict__ fb2) {
    __shared__ float xs[128];
    __shared__ float red[64];
    int row = blockIdx.x, t = threadIdx.x;
    xs[t]      = X[row * 128 + t];
    xs[t + 64] = X[row * 128 + t + 64];
    __syncthreads();
    for (int m = 0; m < 4; m++) {
        const float* W1 = (m == 0) ? cW1 : fW1 + (m - 1) * 128 * 64;
        const float* b1 = (m == 0) ? cb1 : fb1 + (m - 1) * 64;
        const float* W2 = (m == 0) ? cW2 : fW2 + (m - 1) * 64;
        float bb2 = (m == 0) ? cb2[0] : fb2[m - 1];
        float a = b1[t];
        #pragma unroll 8
        for (int d = 0; d < 128; d++) a = fmaf(xs[d], W1[d * 64 + t], a);
        float hv = fmaxf(a, 0.f);
        red[t] = hv * W2[t];
        __syncthreads();
        for (int s = 32; s > 0; s >>= 1) { if (t < s) red[t] += red[t + s]; __syncthreads(); }
        if (t == 0) {
            float v = 1.f / (1.f + expf(-(red[0] + bb2)));
            if (m == 0) g_kap[row] = v; else g_f[m - 1][row] = v;
        }
        __syncthreads();
    }
}

// ---------------- per-batch rank of kappa (desc value, asc index = top_k order) ----------------
__device__ __forceinline__ bool before_cmp(float va, int ia, float vb, int ib) {
    return (va > vb) || (va == vb && ia < ib);
}
__global__ void k_rank() {
    __shared__ float sv[512];
    __shared__ int   si[512];
    int b = blockIdx.x, t = threadIdx.x;
    sv[t] = g_kap[b * 512 + t];
    si[t] = t;
    __syncthreads();
    for (int k = 2; k <= 512; k <<= 1) {
        for (int j = k >> 1; j > 0; j >>= 1) {
            int ixj = t ^ j;
            if (ixj > t) {
                float va = sv[t], vb = sv[ixj];
                int ia = si[t], ib = si[ixj];
                bool up = ((t & k) == 0);
                bool sw = up ? before_cmp(vb, ib, va, ia) : before_cmp(va, ia, vb, ib);
                if (sw) { sv[t] = vb; si[t] = ib; sv[ixj] = va; si[ixj] = ia; }
            }
            __syncthreads();
        }
    }
    g_rank[b * 512 + si[t]] = t;
}

// ---------------- deterministic CSR build from binary A ----------------
__global__ void k_adj(const float* __restrict__ A) {
    int row = blockIdx.x, t = threadIdx.x;
    bool flag = A[(size_t)row * 512 + t] != 0.f;
    unsigned m = __ballot_sync(0xffffffffu, flag);
    int lane = t & 31, w = t >> 5;
    __shared__ int woff[16];
    if (lane == 0) woff[w] = __popc(m);
    __syncthreads();
    if (t == 0) {
        int s = 0;
        for (int i = 0; i < 16; i++) { int c = woff[i]; woff[i] = s; s += c; }
        g_cnt[row] = s;
    }
    __syncthreads();
    if (flag) {
        int pos = woff[w] + __popc(m & ((1u << lane) - 1u));
        if (pos < MAXDEG) g_adj[row][pos] = t;
    }
}

// ---------------- spmv pass 1: A@f_i, A@f_i^2 ----------------
__global__ void k_spmv1() {
    int row = blockIdx.x, lane = threadIdx.x;
    int base = row & ~511;
    int cnt = min(g_cnt[row], MAXDEG);
    float af[FNN] = {0, 0, 0}, aq[FNN] = {0, 0, 0};
    for (int n = lane; n < cnt; n += 32) {
        int gc = base + g_adj[row][n];
        #pragma unroll
        for (int i = 0; i < FNN; i++) {
            float fv = g_f[i][gc];
            af[i] += fv; aq[i] += fv * fv;
        }
    }
    #pragma unroll
    for (int i = 0; i < FNN; i++) {
        for (int o = 16; o > 0; o >>= 1) {
            af[i] += __shfl_down_sync(0xffffffffu, af[i], o);
            aq[i] += __shfl_down_sync(0xffffffffu, aq[i], o);
        }
    }
    if (lane == 0) {
        #pragma unroll
        for (int i = 0; i < FNN; i++) { g_af[i][row] = af[i]; g_af2[i][row] = aq[i]; }
    }
}

// ---------------- elementwise: gamma, delta_f, f*delta_f ----------------
__global__ void k_elem1() {
    int idx = blockIdx.x * blockDim.x + threadIdx.x;
    if (idx >= FNN * BN) return;
    int i = idx / BN, nd = idx % BN;
    float w1 = g_wm1;
    float f = g_f[i][nd];
    float degw = w1 * (float)g_cnt[nd];
    float wf = w1 * g_af[i][nd];
    float gamma = 0.5f * (f * f * degw - 2.f * f * wf + w1 * g_af2[i][nd]);
    float df = f * degw - wf;
    g_gam[i][nd] = gamma; g_df[i][nd] = df; g_fdf[i][nd] = f * df;
}

// ---------------- spmv pass 2: A@gamma, A@df, A@(f*df) ----------------
__global__ void k_spmv2() {
    int row = blockIdx.x, lane = threadIdx.x;
    int base = row & ~511;
    int cnt = min(g_cnt[row], MAXDEG);
    float ag[FNN] = {0, 0, 0}, ad[FNN] = {0, 0, 0}, afd[FNN] = {0, 0, 0};
    for (int n = lane; n < cnt; n += 32) {
        int gc = base + g_adj[row][n];
        #pragma unroll
        for (int i = 0; i < FNN; i++) {
            ag[i]  += g_gam[i][gc];
            ad[i]  += g_df[i][gc];
            afd[i] += g_fdf[i][gc];
        }
    }
    #pragma unroll
    for (int i = 0; i < FNN; i++) {
        for (int o = 16; o > 0; o >>= 1) {
            ag[i]  += __shfl_down_sync(0xffffffffu, ag[i], o);
            ad[i]  += __shfl_down_sync(0xffffffffu, ad[i], o);
            afd[i] += __shfl_down_sync(0xffffffffu, afd[i], o);
        }
    }
    if (lane == 0) {
        #pragma unroll
        for (int i = 0; i < FNN; i++) { g_ag[i][row] = ag[i]; g_adf[i][row] = ad[i]; g_afdf[i][row] = afd[i]; }
    }
}

// ---------------- curvature loss (single-block deterministic reduce) ----------------
__global__ void k_loss(float* __restrict__ out) {
    __shared__ float red[512];
    int t = threadIdx.x;
    float w1 = g_wm1;
    float acc = 0.f;
    for (int idx = t; idx < FNN * BN; idx += 512) {
        int i = idx / BN, nd = idx % BN;
        float f = g_f[i][nd];
        float degw = w1 * (float)g_cnt[nd];
        float wf = w1 * g_af[i][nd];
        float gamma = g_gam[i][nd];
        float df = g_df[i][nd];
        float dgamma = gamma * degw - w1 * g_ag[i][nd];
        float gfd = 0.5f * (f * df * degw - f * w1 * g_adf[i][nd]
                            - df * wf + w1 * g_afdf[i][nd]);
        float gamma2 = 0.5f * dgamma - gfd;
        acc += fmaxf(g_kap[nd] * gamma - gamma2, 0.f);
    }
    for (int nd = t; nd < BN; nd += 512) acc -= 3.f * g_kap[nd];
    red[t] = acc;
    __syncthreads();
    for (int s = 256; s > 0; s >>= 1) { if (t < s) red[t] += red[t + s]; __syncthreads(); }
    if (t == 0) out[80] = red[0];
}

// ---------------- GIN aggregation: agg = (1+eps)h + (A*mask)@h ----------------
__global__ void k_agg(const float* __restrict__ X, const float* __restrict__ gin_eps,
                      const int* __restrict__ p, int layer) {
    int row = blockIdx.x, d = threadIdx.x;
    int Din = (layer == 0) ? 128 : 64;
    const float* hin = (layer == 0) ? X : g_h[layer - 1];
    float eps = gin_eps[layer];
    int cut = (512 * p[0] * layer) / 100;   // matches int(N*pct/100), cumulative masks nest
    __shared__ int s_col[MAXDEG];
    int cnt = min(g_cnt[row], MAXDEG);
    bool alive = g_rank[row] >= cut;
    for (int n = d; n < cnt; n += blockDim.x) {
        int gc = (row & ~511) + g_adj[row][n];
        s_col[n] = (alive && g_rank[gc] >= cut) ? gc : -1;
    }
    __syncthreads();
    if (d < Din) {
        float acc = 0.f;
        for (int n = 0; n < cnt; n++) {
            int gc = s_col[n];
            if (gc >= 0) acc += hin[gc * Din + d];
        }
        g_agg[row * Din + d] = (1.f + eps) * hin[row * Din + d] + acc;
    }
}

// ---------------- GIN MLP: relu(relu(agg@W1+b1)@W2+b2) ----------------
__global__ void k_mlp(int layer,
                      const float* __restrict__ W1, const float* __restrict__ b1,
                      const float* __restrict__ W2, const float* __restrict__ b2) {
    __shared__ float sx[128];
    __shared__ float sh[64];
    int row = blockIdx.x, t = threadIdx.x;
    int Din = (layer == 0) ? 128 : 64;
    for (int d = t; d < Din; d += 64) sx[d] = g_agg[row * Din + d];
    __syncthreads();
    float a = b1[t];
    for (int d = 0; d < Din; d++) a = fmaf(sx[d], W1[d * 64 + t], a);
    sh[t] = fmaxf(a, 0.f);
    __syncthreads();
    float o = b2[t];
    #pragma unroll 8
    for (int k = 0; k < 64; k++) o = fmaf(sh[k], W2[k * 64 + t], o);
    g_h[layer][row * 64 + t] = fmaxf(o, 0.f);
}

// ---------------- readout: sum over nodes of [X,h1,h2,h3] then @out_W ----------------
__global__ void k_out(const float* __restrict__ X, const float* __restrict__ oW,
                      const float* __restrict__ ob, float* __restrict__ out) {
    __shared__ float S[320];
    int b = blockIdx.x, c = threadIdx.x;
    float acc = 0.f;
    if (c < 128) {
        const float* base = X + ((size_t)b * 512) * 128 + c;
        for (int n = 0; n < 512; n++) acc += base[n * 128];
    } else {
        int l = (c - 128) / 64, cc = (c - 128) % 64;
        const float* base = g_h[l] + ((size_t)b * 512) * 64 + cc;
        for (int n = 0; n < 512; n++) acc += base[n * 64];
    }
    S[c] = acc;
    __syncthreads();
    if (c < 10) {
        float o = ob[c];
        for (int k = 0; k < 320; k++) o = fmaf(S[k], oW[k * 10 + c], o);
        out[b * 10 + c] = o;
    }
}

// ---------------- launch ----------------
extern "C" void kernel_launch(void* const* d_in, const int* in_sizes, int n_in,
                              void* d_out, int out_size) {
    const float* X    = (const float*)d_in[0];
    const float* A    = (const float*)d_in[1];
    const int*   p    = (const int*)  d_in[2];
    const float* cW1  = (const float*)d_in[3];
    const float* cb1  = (const float*)d_in[4];
    const float* cW2  = (const float*)d_in[5];
    const float* cb2  = (const float*)d_in[6];
    const float* wmW1 = (const float*)d_in[7];
    const float* wmb1 = (const float*)d_in[8];
    const float* wmW2 = (const float*)d_in[9];
    const float* wmb2 = (const float*)d_in[10];
    const float* wmW3 = (const float*)d_in[11];
    const float* wmb3 = (const float*)d_in[12];
    const float* fnW1 = (const float*)d_in[13];
    const float* fnb1 = (const float*)d_in[14];
    const float* fnW2 = (const float*)d_in[15];
    const float* fnb2 = (const float*)d_in[16];
    const float* eps  = (const float*)d_in[17];
    const float* g0W1 = (const float*)d_in[18];
    const float* g0b1 = (const float*)d_in[19];
    const float* g0W2 = (const float*)d_in[20];
    const float* g0b2 = (const float*)d_in[21];
    const float* g1W1 = (const float*)d_in[22];
    const float* g1b1 = (const float*)d_in[23];
    const float* g1W2 = (const float*)d_in[24];
    const float* g1b2 = (const float*)d_in[25];
    const float* g2W1 = (const float*)d_in[26];
    const float* g2b1 = (const float*)d_in[27];
    const float* g2W2 = (const float*)d_in[28];
    const float* g2b2 = (const float*)d_in[29];
    const float* oW   = (const float*)d_in[30];
    const float* ob   = (const float*)d_in[31];
    float* out = (float*)d_out;

    k_wm1<<<1, 64>>>(wmW1, wmb1, wmW2, wmb2, wmW3, wmb3);
    k_node<<<BN, 64>>>(X, cW1, cb1, cW2, cb2, fnW1, fnb1, fnW2, fnb2);
    k_rank<<<BB, 512>>>();
    k_adj<<<BN, 512>>>(A);
    k_spmv1<<<BN, 32>>>();
    k_elem1<<<(FNN * BN + 255) / 256, 256>>>();
    k_spmv2<<<BN, 32>>>();
    k_loss<<<1, 512>>>(out);

    k_agg<<<BN, 128>>>(X, eps, p, 0);
    k_mlp<<<BN, 64>>>(0, g0W1, g0b1, g0W2, g0b2);
    k_agg<<<BN, 64>>>(X, eps, p, 1);
    k_mlp<<<BN, 64>>>(1, g1W1, g1b1, g1W2, g1b2);
    k_agg<<<BN, 64>>>(X, eps, p, 2);
    k_mlp<<<BN, 64>>>(2, g2W1, g2b1, g2W2, g2b2);

    k_out<<<BB, 320>>>(X, oW, ob, out);
}